// round 4
// baseline (speedup 1.0000x reference)
#include <cuda_runtime.h>
#include <cstdint>
#include <math.h>

#define DIM 256
#define TM 128
#define THREADS 512

#define PX 68                    // X row stride (68 % 32 == 4): scalar A loads conflict-free
#define PW 72                    // W row stride (72 % 32 == 8): float2 B loads conflict-free
#define GW 264                   // g_Wt gmem row stride
#define XS_FLOATS (128 * PX)     // 8704
#define WS_FLOATS (256 * PW)     // 18432
#define BUF_FLOATS (XS_FLOATS + WS_FLOATS)
#define SMEM_BYTES (2 * BUF_FLOATS * 4)   // 217088

__device__ float g_Wt[4][256 * GW];   // [n][k] transposed, tf32-rounded, k-pair interleaved

__device__ __forceinline__ uint32_t smem_u32(const void* p) {
    uint32_t a;
    asm("{ .reg .u64 t; cvta.to.shared.u64 t, %1; cvt.u32.u64 %0, t; }" : "=r"(a) : "l"(p));
    return a;
}
__device__ __forceinline__ void cp16(uint32_t s, const float* g) {
    asm volatile("cp.async.cg.shared.global [%0], [%1], 16;" :: "r"(s), "l"(g));
}
#define CP_COMMIT() asm volatile("cp.async.commit_group;" ::: "memory")
#define CP_WAIT1()  asm volatile("cp.async.wait_group 1;" ::: "memory")
#define CP_WAIT0()  asm volatile("cp.async.wait_group 0;" ::: "memory")

__device__ __forceinline__ uint32_t to_tf32(float x) {
    uint32_t r;
    asm("cvt.rna.tf32.f32 %0, %1;" : "=r"(r) : "f"(x));
    return r;
}
__device__ __forceinline__ void mma8(float* c, const uint32_t* a, const uint32_t* b) {
    asm volatile(
        "mma.sync.aligned.m16n8k8.row.col.f32.tf32.tf32.f32 "
        "{%0,%1,%2,%3}, {%4,%5,%6,%7}, {%8,%9}, {%0,%1,%2,%3};"
        : "+f"(c[0]), "+f"(c[1]), "+f"(c[2]), "+f"(c[3])
        : "r"(a[0]), "r"(a[1]), "r"(a[2]), "r"(a[3]), "r"(b[0]), "r"(b[1]));
}

// interleave: within each 8-k group, pos = 2*(k%4) + ((k>>2)&1), so (k, k+4) adjacent
__device__ __forceinline__ int kpos(int k) {
    return (k & ~7) + ((k & 3) * 2) + ((k >> 2) & 1);
}

// ---------- one KC=64 chunk of [128 x 256] += X(128xKC) @ W(KCx256) ----------
template <bool SCALE>
__device__ __forceinline__ void gemm_chunk(const float* __restrict__ xs,
                                           const float* __restrict__ ws,
                                           float (&acc)[2][8][4],
                                           const float (&sc)[2][2],
                                           int wm, int wn, int lq, int lr) {
#pragma unroll
    for (int ks = 0; ks < 8; ++ks) {
        uint32_t ua[2][4];
#pragma unroll
        for (int mt = 0; mt < 2; ++mt) {
            const int r = wm * 32 + mt * 16 + lq;
            const int c = ks * 8 + lr;
            float a0 = xs[r * PX + c];
            float a1 = xs[(r + 8) * PX + c];
            float a2 = xs[r * PX + c + 4];
            float a3 = xs[(r + 8) * PX + c + 4];
            if (SCALE) {
                a0 *= sc[mt][0]; a1 *= sc[mt][1];
                a2 *= sc[mt][0]; a3 *= sc[mt][1];
            }
            ua[mt][0] = to_tf32(a0); ua[mt][1] = to_tf32(a1);
            ua[mt][2] = to_tf32(a2); ua[mt][3] = to_tf32(a3);
        }
#pragma unroll
        for (int nt = 0; nt < 8; ++nt) {
            const int n = wn * 64 + nt * 8 + lq;
            float2 bv = *reinterpret_cast<const float2*>(ws + n * PW + ks * 8 + 2 * lr);
            uint32_t b[2] = { __float_as_uint(bv.x), __float_as_uint(bv.y) };
            mma8(acc[0][nt], ua[0], b);
            mma8(acc[1][nt], ua[1], b);
        }
    }
}

__device__ __forceinline__ void zero_acc(float (&acc)[2][8][4]) {
#pragma unroll
    for (int mt = 0; mt < 2; ++mt)
#pragma unroll
        for (int nt = 0; nt < 8; ++nt)
#pragma unroll
            for (int q = 0; q < 4; ++q) acc[mt][nt][q] = 0.f;
}

__device__ __forceinline__ void gate_dot(const float* __restrict__ Xo,
                                         const float (&acc)[2][8][4], int g,
                                         int wm, int wn, int lq, int lr,
                                         float (*s_g)[4][128]) {
    float pr[2][2] = {{0.f, 0.f}, {0.f, 0.f}};
#pragma unroll
    for (int mt = 0; mt < 2; ++mt) {
        const int r0 = wm * 32 + mt * 16 + lq;
#pragma unroll
        for (int nt = 0; nt < 8; ++nt) {
            const int cb = wn * 64 + nt * 8 + lr * 2;
            float2 v0 = *reinterpret_cast<const float2*>(Xo + (size_t)r0 * DIM + cb);
            float2 v1 = *reinterpret_cast<const float2*>(Xo + (size_t)(r0 + 8) * DIM + cb);
            pr[mt][0] += acc[mt][nt][0] * v0.x + acc[mt][nt][1] * v0.y;
            pr[mt][1] += acc[mt][nt][2] * v1.x + acc[mt][nt][3] * v1.y;
        }
    }
#pragma unroll
    for (int off = 1; off <= 2; off <<= 1)
#pragma unroll
        for (int mt = 0; mt < 2; ++mt) {
            pr[mt][0] += __shfl_xor_sync(0xFFFFFFFFu, pr[mt][0], off);
            pr[mt][1] += __shfl_xor_sync(0xFFFFFFFFu, pr[mt][1], off);
        }
    if (lr == 0) {
#pragma unroll
        for (int mt = 0; mt < 2; ++mt) {
            s_g[g][wn][wm * 32 + mt * 16 + lq] = pr[mt][0];
            s_g[g][wn][wm * 32 + mt * 16 + lq + 8] = pr[mt][1];
        }
    }
}

__global__ void __launch_bounds__(THREADS, 1)
fused_mma_kernel(const float* __restrict__ i0, const float* __restrict__ i1,
                 float* __restrict__ out) {
    extern __shared__ float dyn[];
    __shared__ float s_g[2][4][128];
    __shared__ float s_sc[2][128];

    const int tid = threadIdx.x;
    const int l = tid & 31, w = tid >> 5;
    const int wm = w >> 2, wn = w & 3;
    const int lq = l >> 2, lr = l & 3;
    const size_t rowbase = (size_t)blockIdx.x * TM;
    const float* X0g = i0 + rowbase * DIM;
    const float* X1g = i1 + rowbase * DIM;
    const uint32_t sb = smem_u32(dyn);

    // jobs 0..15: pass p=j>>2, chunk c=j&3
    //  p0: A=X1, B=Wt[0](attn1) -> g0 dot X0    p1: A=X0, B=Wt[1](attn2) -> g1 dot X1
    //  p2: A=X0, B=Wt[2](W1), scale s0          p3: A=X1, B=Wt[3](W2), scale s1
    auto stage = [&](int j) {
        const int p = j >> 2, c = j & 3;
        const float* As = (p == 0 || p == 3) ? X1g : X0g;
        const float* Bs = g_Wt[p];
        const uint32_t xb = sb + (uint32_t)(j & 1) * (BUF_FLOATS * 4);
        const uint32_t wb = xb + XS_FLOATS * 4;
#pragma unroll
        for (int t = 0; t < 4; ++t) {           // X chunk: 128 x 64
            const int id = tid + t * THREADS;
            const int r = id >> 4, c4 = (id & 15) << 2;
            cp16(xb + (uint32_t)(r * PX + c4) * 4, As + (size_t)r * DIM + c * 64 + c4);
        }
#pragma unroll
        for (int t = 0; t < 8; ++t) {           // W chunk: 256 x 64 (pre-transposed)
            const int id = tid + t * THREADS;
            const int n = id >> 4, k4 = (id & 15) << 2;
            cp16(wb + (uint32_t)(n * PW + k4) * 4, Bs + (size_t)n * GW + c * 64 + k4);
        }
        CP_COMMIT();
    };

    float acc[2][8][4];
    zero_acc(acc);
    float sc[2][2] = {{1.f, 1.f}, {1.f, 1.f}};

    stage(0);
    stage(1);

    for (int j = 0; j < 16; ++j) {
        if (j == 15) { CP_WAIT0(); } else { CP_WAIT1(); }
        __syncthreads();
        const float* xs = dyn + (j & 1) * BUF_FLOATS;
        const float* ws = xs + XS_FLOATS;
        if (j >= 8) gemm_chunk<true>(xs, ws, acc, sc, wm, wn, lq, lr);
        else        gemm_chunk<false>(xs, ws, acc, sc, wm, wn, lq, lr);

        if (j == 3) {
            gate_dot(X0g, acc, 0, wm, wn, lq, lr, s_g);
            zero_acc(acc);
        }
        if (j == 7) {
            gate_dot(X1g, acc, 1, wm, wn, lq, lr, s_g);
            __syncthreads();
            if (tid < 128) {
                const float g0 = s_g[0][0][tid] + s_g[0][1][tid] + s_g[0][2][tid] + s_g[0][3][tid];
                const float g1 = s_g[1][0][tid] + s_g[1][1][tid] + s_g[1][2][tid] + s_g[1][3][tid];
                s_sc[0][tid] = 1.f + 1.f / (1.f + expf(-g0));
                s_sc[1][tid] = 1.f + 1.f / (1.f + expf(-g1));
            }
            __syncthreads();
#pragma unroll
            for (int mt = 0; mt < 2; ++mt) {
                sc[mt][0] = s_sc[0][wm * 32 + mt * 16 + lq];
                sc[mt][1] = s_sc[0][wm * 32 + mt * 16 + lq + 8];
            }
            zero_acc(acc);
        }
        if (j == 11) {
#pragma unroll
            for (int mt = 0; mt < 2; ++mt) {
                sc[mt][0] = s_sc[1][wm * 32 + mt * 16 + lq];
                sc[mt][1] = s_sc[1][wm * 32 + mt * 16 + lq + 8];
            }
        }
        __syncthreads();
        if (j + 2 < 16) stage(j + 2);
    }

    // epilogue: out = s0*(X0@W1) + s1*(X1@W2) already accumulated
#pragma unroll
    for (int mt = 0; mt < 2; ++mt) {
        const int r0 = wm * 32 + mt * 16 + lq;
#pragma unroll
        for (int nt = 0; nt < 8; ++nt) {
            const int cb = wn * 64 + nt * 8 + lr * 2;
            float2 v0 = make_float2(acc[mt][nt][0], acc[mt][nt][1]);
            float2 v1 = make_float2(acc[mt][nt][2], acc[mt][nt][3]);
            *reinterpret_cast<float2*>(out + (rowbase + r0) * DIM + cb) = v0;
            *reinterpret_cast<float2*>(out + (rowbase + r0 + 8) * DIM + cb) = v1;
        }
    }
}

// prep: g_Wt[z][n][kpos(k)] = tf32_rna(W_z[k][n])  (transpose + round + interleave)
__global__ void wprep_kernel(const float* __restrict__ w1, const float* __restrict__ w2,
                             const float* __restrict__ a1, const float* __restrict__ a2) {
    const int z = blockIdx.x;
    const float* src = (z == 0) ? a1 : (z == 1) ? a2 : (z == 2) ? w1 : w2;
    const int n = threadIdx.x;
    const int k0 = blockIdx.y * 32;
    for (int k = k0; k < k0 + 32; ++k) {
        float v = src[k * DIM + n];
        g_Wt[z][n * GW + kpos(k)] = __uint_as_float(to_tf32(v));
    }
}

extern "C" void kernel_launch(void* const* d_in, const int* in_sizes, int n_in,
                              void* d_out, int out_size) {
    const float* i0 = (const float*)d_in[0];
    const float* i1 = (const float*)d_in[1];
    const float* W1 = (const float*)d_in[2];
    const float* W2 = (const float*)d_in[3];
    const float* A1 = (const float*)d_in[4];
    const float* A2 = (const float*)d_in[5];
    float* out = (float*)d_out;

    wprep_kernel<<<dim3(4, 8), 256>>>(W1, W2, A1, A2);

    cudaFuncSetAttribute(fused_mma_kernel,
                         cudaFuncAttributeMaxDynamicSharedMemorySize, SMEM_BYTES);
    const int rows = in_sizes[0] / DIM;          // 65536
    fused_mma_kernel<<<rows / TM, THREADS, SMEM_BYTES>>>(i0, i1, out);
    (void)n_in; (void)out_size;
}

// round 5
// speedup vs baseline: 1.6192x; 1.6192x over previous
#include <cuda_runtime.h>
#include <cstdint>
#include <math.h>

#define DIM 256
#define TM 128
#define THREADS 256

#define PX 68                    // X smem row stride: 68 % 32 == 4 -> A LDS.32 conflict-free
#define PW 72                    // Wt smem row stride: 72 % 32 == 8 -> B LDS.64 conflict-free
#define GW 256                   // g_Wt gmem row stride (1KB rows, coalesced staging)
#define XS_FLOATS (128 * PX)     // 8704
#define WS_FLOATS (256 * PW)     // 18432
#define BUF_FLOATS (XS_FLOATS + WS_FLOATS)
#define SMEM_BYTES (2 * BUF_FLOATS * 4)   // 217088

__device__ float g_Wt[4][256 * GW];   // [n][k]: transposed, tf32-rna-rounded, k-interleaved

__device__ __forceinline__ uint32_t smem_u32(const void* p) {
    uint32_t a;
    asm("{ .reg .u64 t; cvta.to.shared.u64 t, %1; cvt.u32.u64 %0, t; }" : "=r"(a) : "l"(p));
    return a;
}
__device__ __forceinline__ void cp16(uint32_t s, const float* g) {
    asm volatile("cp.async.cg.shared.global [%0], [%1], 16;" :: "r"(s), "l"(g));
}
#define CP_COMMIT() asm volatile("cp.async.commit_group;" ::: "memory")
#define CP_WAIT1()  asm volatile("cp.async.wait_group 1;" ::: "memory")
#define CP_WAIT0()  asm volatile("cp.async.wait_group 0;" ::: "memory")

__device__ __forceinline__ uint32_t to_tf32(float x) {
    uint32_t r;
    asm("cvt.rna.tf32.f32 %0, %1;" : "=r"(r) : "f"(x));
    return r;
}
__device__ __forceinline__ void mma8(float* c, const uint32_t* a, const uint32_t* b) {
    asm volatile(
        "mma.sync.aligned.m16n8k8.row.col.f32.tf32.tf32.f32 "
        "{%0,%1,%2,%3}, {%4,%5,%6,%7}, {%8,%9}, {%0,%1,%2,%3};"
        : "+f"(c[0]), "+f"(c[1]), "+f"(c[2]), "+f"(c[3])
        : "r"(a[0]), "r"(a[1]), "r"(a[2]), "r"(a[3]), "r"(b[0]), "r"(b[1]));
}

// within each 8-k group: pos = 2*(k%4) + ((k>>2)&1)  -> (k, k+4) adjacent
__device__ __forceinline__ int kpos(int k) {
    return (k & ~7) + ((k & 3) * 2) + ((k >> 2) & 1);
}

// ---------- one KC=64 chunk of [128 x 256] += X(128xKC) @ W(KCx256) ----------
// warptile 32 x 128: wm in 0..3 (rows), wn in 0..1 (cols)
template <bool SCALE>
__device__ __forceinline__ void gemm_chunk(const float* __restrict__ xs,
                                           const float* __restrict__ ws,
                                           float (&acc)[2][16][4],
                                           const float (&sc)[2][2],
                                           int wm, int wn, int lq, int lr) {
#pragma unroll
    for (int ks = 0; ks < 8; ++ks) {
        uint32_t ua[2][4];
#pragma unroll
        for (int mt = 0; mt < 2; ++mt) {
            const int r = wm * 32 + mt * 16 + lq;
            const int c = ks * 8 + lr;
            float a0 = xs[r * PX + c];
            float a1 = xs[(r + 8) * PX + c];
            float a2 = xs[r * PX + c + 4];
            float a3 = xs[(r + 8) * PX + c + 4];
            if (SCALE) {
                a0 *= sc[mt][0]; a1 *= sc[mt][1];
                a2 *= sc[mt][0]; a3 *= sc[mt][1];
            }
            ua[mt][0] = __float_as_uint(a0);   // raw fp32 -> tf32 truncation in HW
            ua[mt][1] = __float_as_uint(a1);
            ua[mt][2] = __float_as_uint(a2);
            ua[mt][3] = __float_as_uint(a3);
        }
#pragma unroll
        for (int nt = 0; nt < 16; ++nt) {
            const int n = wn * 128 + nt * 8 + lq;
            float2 bv = *reinterpret_cast<const float2*>(ws + n * PW + ks * 8 + 2 * lr);
            uint32_t b[2] = { __float_as_uint(bv.x), __float_as_uint(bv.y) };
            mma8(acc[0][nt], ua[0], b);
            mma8(acc[1][nt], ua[1], b);
        }
    }
}

__device__ __forceinline__ void zero_acc(float (&acc)[2][16][4]) {
#pragma unroll
    for (int mt = 0; mt < 2; ++mt)
#pragma unroll
        for (int nt = 0; nt < 16; ++nt)
#pragma unroll
            for (int q = 0; q < 4; ++q) acc[mt][nt][q] = 0.f;
}

__device__ __forceinline__ void gate_dot(const float* __restrict__ Xo,
                                         const float (&acc)[2][16][4], int g,
                                         int wm, int wn, int lq, int lr,
                                         float (*s_g)[2][128]) {
    float pr[2][2] = {{0.f, 0.f}, {0.f, 0.f}};
#pragma unroll
    for (int mt = 0; mt < 2; ++mt) {
        const int r0 = wm * 32 + mt * 16 + lq;
#pragma unroll
        for (int nt = 0; nt < 16; ++nt) {
            const int cb = wn * 128 + nt * 8 + lr * 2;
            float2 v0 = *reinterpret_cast<const float2*>(Xo + (size_t)r0 * DIM + cb);
            float2 v1 = *reinterpret_cast<const float2*>(Xo + (size_t)(r0 + 8) * DIM + cb);
            pr[mt][0] += acc[mt][nt][0] * v0.x + acc[mt][nt][1] * v0.y;
            pr[mt][1] += acc[mt][nt][2] * v1.x + acc[mt][nt][3] * v1.y;
        }
    }
#pragma unroll
    for (int off = 1; off <= 2; off <<= 1)
#pragma unroll
        for (int mt = 0; mt < 2; ++mt) {
            pr[mt][0] += __shfl_xor_sync(0xFFFFFFFFu, pr[mt][0], off);
            pr[mt][1] += __shfl_xor_sync(0xFFFFFFFFu, pr[mt][1], off);
        }
    if (lr == 0) {
#pragma unroll
        for (int mt = 0; mt < 2; ++mt) {
            s_g[g][wn][wm * 32 + mt * 16 + lq] = pr[mt][0];
            s_g[g][wn][wm * 32 + mt * 16 + lq + 8] = pr[mt][1];
        }
    }
}

__global__ void __launch_bounds__(THREADS, 1)
fused_mma_kernel(const float* __restrict__ i0, const float* __restrict__ i1,
                 float* __restrict__ out) {
    extern __shared__ float dyn[];
    __shared__ float s_g[2][2][128];
    __shared__ float s_sc[2][128];

    const int tid = threadIdx.x;
    const int l = tid & 31, w = tid >> 5;
    const int wm = w >> 1, wn = w & 1;
    const int lq = l >> 2, lr = l & 3;
    const size_t rowbase = (size_t)blockIdx.x * TM;
    const float* X0g = i0 + rowbase * DIM;
    const float* X1g = i1 + rowbase * DIM;
    const uint32_t sb = smem_u32(dyn);

    // jobs 0..15: pass p=j>>2, chunk c=j&3
    //  p0: A=X1, B=Wt[0](attn1) -> g0 dot X0    p1: A=X0, B=Wt[1](attn2) -> g1 dot X1
    //  p2: A=X0, B=Wt[2](W1), scale s0          p3: A=X1, B=Wt[3](W2), scale s1
    auto stage = [&](int j) {
        const int p = j >> 2, c = j & 3;
        const float* As = (p == 0 || p == 3) ? X1g : X0g;
        const float* Bs = g_Wt[p];
        const uint32_t xb = sb + (uint32_t)(j & 1) * (BUF_FLOATS * 4);
        const uint32_t wb = xb + XS_FLOATS * 4;
#pragma unroll
        for (int t = 0; t < 8; ++t) {          // X chunk: 128 x 64
            const int id = tid + t * THREADS;
            const int r = id >> 4, c4 = (id & 15) << 2;
            cp16(xb + (uint32_t)(r * PX + c4) * 4, As + (size_t)r * DIM + c * 64 + c4);
        }
#pragma unroll
        for (int t = 0; t < 16; ++t) {         // Wt chunk: 256 n x 64 k
            const int id = tid + t * THREADS;
            const int n = id >> 4, k4 = (id & 15) << 2;
            cp16(wb + (uint32_t)(n * PW + k4) * 4, Bs + (size_t)n * GW + c * 64 + k4);
        }
        CP_COMMIT();
    };

    float acc[2][16][4];
    zero_acc(acc);
    float sc[2][2] = {{1.f, 1.f}, {1.f, 1.f}};

    stage(0);
    stage(1);

    for (int j = 0; j < 16; ++j) {
        if (j == 15) { CP_WAIT0(); } else { CP_WAIT1(); }
        __syncthreads();
        const float* xs = dyn + (j & 1) * BUF_FLOATS;
        const float* ws = xs + XS_FLOATS;
        if (j >= 8) gemm_chunk<true>(xs, ws, acc, sc, wm, wn, lq, lr);
        else        gemm_chunk<false>(xs, ws, acc, sc, wm, wn, lq, lr);

        if (j == 3) {
            gate_dot(X0g, acc, 0, wm, wn, lq, lr, s_g);
            zero_acc(acc);
        }
        if (j == 7) {
            gate_dot(X1g, acc, 1, wm, wn, lq, lr, s_g);
            __syncthreads();
            if (tid < 128) {
                const float g0 = s_g[0][0][tid] + s_g[0][1][tid];
                const float g1 = s_g[1][0][tid] + s_g[1][1][tid];
                s_sc[0][tid] = 1.f + 1.f / (1.f + expf(-g0));
                s_sc[1][tid] = 1.f + 1.f / (1.f + expf(-g1));
            }
            __syncthreads();
#pragma unroll
            for (int mt = 0; mt < 2; ++mt) {
                sc[mt][0] = s_sc[0][wm * 32 + mt * 16 + lq];
                sc[mt][1] = s_sc[0][wm * 32 + mt * 16 + lq + 8];
            }
            zero_acc(acc);
        }
        if (j == 11) {
#pragma unroll
            for (int mt = 0; mt < 2; ++mt) {
                sc[mt][0] = s_sc[1][wm * 32 + mt * 16 + lq];
                sc[mt][1] = s_sc[1][wm * 32 + mt * 16 + lq + 8];
            }
        }
        __syncthreads();
        if (j + 2 < 16) stage(j + 2);
    }

    // epilogue: out = s0*(X0@W1) + s1*(X1@W2) already accumulated
#pragma unroll
    for (int mt = 0; mt < 2; ++mt) {
        const int r0 = wm * 32 + mt * 16 + lq;
#pragma unroll
        for (int nt = 0; nt < 16; ++nt) {
            const int cb = wn * 128 + nt * 8 + lr * 2;
            float2 v0 = make_float2(acc[mt][nt][0], acc[mt][nt][1]);
            float2 v1 = make_float2(acc[mt][nt][2], acc[mt][nt][3]);
            *reinterpret_cast<float2*>(out + (rowbase + r0) * DIM + cb) = v0;
            *reinterpret_cast<float2*>(out + (rowbase + r0 + 8) * DIM + cb) = v1;
        }
    }
}

// prep: g_Wt[z][n*GW + kpos(k)] = tf32_rna(W_z[k][n])
__global__ void wprep_kernel(const float* __restrict__ w1, const float* __restrict__ w2,
                             const float* __restrict__ a1, const float* __restrict__ a2) {
    const int z = blockIdx.x;
    const float* src = (z == 0) ? a1 : (z == 1) ? a2 : (z == 2) ? w1 : w2;
    const int n = threadIdx.x;
    const int k0 = blockIdx.y * 32;
    for (int k = k0; k < k0 + 32; ++k) {
        float v = src[k * DIM + n];
        g_Wt[z][n * GW + kpos(k)] = __uint_as_float(to_tf32(v));
    }
}

extern "C" void kernel_launch(void* const* d_in, const int* in_sizes, int n_in,
                              void* d_out, int out_size) {
    const float* i0 = (const float*)d_in[0];
    const float* i1 = (const float*)d_in[1];
    const float* W1 = (const float*)d_in[2];
    const float* W2 = (const float*)d_in[3];
    const float* A1 = (const float*)d_in[4];
    const float* A2 = (const float*)d_in[5];
    float* out = (float*)d_out;

    wprep_kernel<<<dim3(4, 8), 256>>>(W1, W2, A1, A2);

    cudaFuncSetAttribute(fused_mma_kernel,
                         cudaFuncAttributeMaxDynamicSharedMemorySize, SMEM_BYTES);
    const int rows = in_sizes[0] / DIM;          // 65536
    fused_mma_kernel<<<rows / TM, THREADS, SMEM_BYTES>>>(i0, i1, out);
    (void)n_in; (void)out_size;
}